// round 5
// baseline (speedup 1.0000x reference)
#include <cuda_runtime.h>
#include <cuda_fp16.h>
#include <cstdint>

#define NV   50000
#define ME   10000
#define NNZt 1600000
#define D    128

#define NBLK_E ((ME + 1023) / 1024)   // 10
#define NBLK_V ((NV + 1023) / 1024)   // 49

// ---------------------------------------------------------------------------
// Static device scratch
// ---------------------------------------------------------------------------
__device__ __half g_Xh[NV * D];       // 12.8 MB  fp16 copy of X
__device__ __half g_Xe[ME * D];       // 2.56 MB  edge means (fp16)
__device__ float  g_Xi[NV * D];       // 25.6 MB  mixed vertex features
__device__ int    g_histE[ME];
__device__ int    g_histV[NV];
__device__ int    g_offE[ME];
__device__ int    g_offV[NV];
__device__ int    g_curE[ME];
__device__ int    g_curV[NV];
__device__ int    g_vlistE[NNZt];
__device__ int    g_elistV[NNZt];
__device__ int    g_bsumE[64];
__device__ int    g_bsumV[64];

// ---------------------------------------------------------------------------
// Convert X to fp16
// ---------------------------------------------------------------------------
__global__ void convert_kernel(const float* __restrict__ X) {
    int i = blockIdx.x * blockDim.x + threadIdx.x;
    const int n4 = NV * D / 4;
    if (i >= n4) return;
    float4 v = __ldg(&reinterpret_cast<const float4*>(X)[i]);
    __half2 h0 = __floats2half2_rn(v.x, v.y);
    __half2 h1 = __floats2half2_rn(v.z, v.w);
    uint2 o;
    o.x = *reinterpret_cast<unsigned*>(&h0);
    o.y = *reinterpret_cast<unsigned*>(&h1);
    reinterpret_cast<uint2*>(g_Xh)[i] = o;
}

__global__ void zero_hist_kernel() {
    int i = blockIdx.x * blockDim.x + threadIdx.x;
    if (i < ME) g_histE[i] = 0;
    if (i < NV) g_histV[i] = 0;
}

// ---------------------------------------------------------------------------
// Histogram: 8 entries per thread (2x int4, 8 independent atomics in flight)
// ---------------------------------------------------------------------------
__global__ void hist_kernel(const int* __restrict__ vertex,
                            const int* __restrict__ edges) {
    int i0 = (blockIdx.x * blockDim.x + threadIdx.x) * 8;
    if (i0 >= NNZt) return;
    int4 va = __ldg(reinterpret_cast<const int4*>(vertex + i0));
    int4 vb = __ldg(reinterpret_cast<const int4*>(vertex + i0 + 4));
    int4 ea = __ldg(reinterpret_cast<const int4*>(edges + i0));
    int4 eb = __ldg(reinterpret_cast<const int4*>(edges + i0 + 4));
    atomicAdd(&g_histE[ea.x], 1); atomicAdd(&g_histE[ea.y], 1);
    atomicAdd(&g_histE[ea.z], 1); atomicAdd(&g_histE[ea.w], 1);
    atomicAdd(&g_histE[eb.x], 1); atomicAdd(&g_histE[eb.y], 1);
    atomicAdd(&g_histE[eb.z], 1); atomicAdd(&g_histE[eb.w], 1);
    atomicAdd(&g_histV[va.x], 1); atomicAdd(&g_histV[va.y], 1);
    atomicAdd(&g_histV[va.z], 1); atomicAdd(&g_histV[va.w], 1);
    atomicAdd(&g_histV[vb.x], 1); atomicAdd(&g_histV[vb.y], 1);
    atomicAdd(&g_histV[vb.z], 1); atomicAdd(&g_histV[vb.w], 1);
}

// ---------------------------------------------------------------------------
// Multi-block exclusive scan, 3 phases.
// Phase A: per-block (1024 elems) partial sums.
// ---------------------------------------------------------------------------
__global__ __launch_bounds__(256) void scanA_kernel() {
    int b = blockIdx.x;
    const int* hist; int n, bl; int* bsum;
    if (b < NBLK_E) { hist = g_histE; n = ME; bl = b;          bsum = g_bsumE; }
    else            { hist = g_histV; n = NV; bl = b - NBLK_E; bsum = g_bsumV; }
    int t = threadIdx.x;
    int i0 = bl * 1024 + t * 4;
    int s = 0;
    if (i0 < n) {
        int4 v = *reinterpret_cast<const int4*>(hist + i0);
        s = v.x + v.y + v.z + v.w;
    }
    __shared__ int sm[256];
    sm[t] = s; __syncthreads();
    for (int d = 128; d > 0; d >>= 1) {
        if (t < d) sm[t] += sm[t + d];
        __syncthreads();
    }
    if (t == 0) bsum[bl] = sm[0];
}

// Phase B: scan the block sums (one small block; two 64-wide ladders)
__global__ __launch_bounds__(128) void scanB_kernel() {
    __shared__ int sv[64], se[64];
    int t = threadIdx.x;
    int o = 0;
    if (t < 64) { o = (t < NBLK_V) ? g_bsumV[t] : 0; sv[t] = o; }
    else        { int u = t - 64; o = (u < NBLK_E) ? g_bsumE[u] : 0; se[u] = o; }
    __syncthreads();
    for (int d = 1; d < 64; d <<= 1) {
        int x;
        if (t < 64) x = (t >= d) ? sv[t - d] : 0;
        else        { int u = t - 64; x = (u >= d) ? se[u - d] : 0; }
        __syncthreads();
        if (t < 64) sv[t] += x; else se[t - 64] += x;
        __syncthreads();
    }
    if (t < 64) { if (t < NBLK_V) g_bsumV[t] = sv[t] - o; }
    else        { int u = t - 64; if (u < NBLK_E) g_bsumE[u] = se[u] - o; }
}

// Phase C: per-block prefix, add block offset, write off/cur (int4 stores)
__global__ __launch_bounds__(256) void scanC_kernel() {
    int b = blockIdx.x;
    const int* hist; int n, bl; int *off, *cur; const int* bsum;
    if (b < NBLK_E) { hist = g_histE; n = ME; bl = b;          off = g_offE; cur = g_curE; bsum = g_bsumE; }
    else            { hist = g_histV; n = NV; bl = b - NBLK_E; off = g_offV; cur = g_curV; bsum = g_bsumV; }
    int t = threadIdx.x;
    int i0 = bl * 1024 + t * 4;
    int4 v = make_int4(0, 0, 0, 0);
    int s = 0;
    if (i0 < n) {
        v = *reinterpret_cast<const int4*>(hist + i0);
        s = v.x + v.y + v.z + v.w;
    }
    __shared__ int sm[256];
    sm[t] = s; __syncthreads();
    for (int d = 1; d < 256; d <<= 1) {
        int x = (t >= d) ? sm[t - d] : 0;
        __syncthreads();
        sm[t] += x;
        __syncthreads();
    }
    if (i0 < n) {
        int run = bsum[bl] + sm[t] - s;  // exclusive prefix
        int4 o;
        o.x = run; run += v.x;
        o.y = run; run += v.y;
        o.z = run; run += v.z;
        o.w = run;
        *reinterpret_cast<int4*>(off + i0) = o;
        *reinterpret_cast<int4*>(cur + i0) = o;
    }
}

// ---------------------------------------------------------------------------
// Permute: 8 entries per thread -> 8 independent atomic+store chains
// ---------------------------------------------------------------------------
__global__ void permute_kernel(const int* __restrict__ vertex,
                               const int* __restrict__ edges) {
    int i0 = (blockIdx.x * blockDim.x + threadIdx.x) * 8;
    if (i0 >= NNZt) return;
    int4 va = __ldg(reinterpret_cast<const int4*>(vertex + i0));
    int4 vb = __ldg(reinterpret_cast<const int4*>(vertex + i0 + 4));
    int4 ea = __ldg(reinterpret_cast<const int4*>(edges + i0));
    int4 eb = __ldg(reinterpret_cast<const int4*>(edges + i0 + 4));
    int p0 = atomicAdd(&g_curE[ea.x], 1);
    int p1 = atomicAdd(&g_curE[ea.y], 1);
    int p2 = atomicAdd(&g_curE[ea.z], 1);
    int p3 = atomicAdd(&g_curE[ea.w], 1);
    int p4 = atomicAdd(&g_curE[eb.x], 1);
    int p5 = atomicAdd(&g_curE[eb.y], 1);
    int p6 = atomicAdd(&g_curE[eb.z], 1);
    int p7 = atomicAdd(&g_curE[eb.w], 1);
    g_vlistE[p0] = va.x; g_vlistE[p1] = va.y;
    g_vlistE[p2] = va.z; g_vlistE[p3] = va.w;
    g_vlistE[p4] = vb.x; g_vlistE[p5] = vb.y;
    g_vlistE[p6] = vb.z; g_vlistE[p7] = vb.w;
    int q0 = atomicAdd(&g_curV[va.x], 1);
    int q1 = atomicAdd(&g_curV[va.y], 1);
    int q2 = atomicAdd(&g_curV[va.z], 1);
    int q3 = atomicAdd(&g_curV[va.w], 1);
    int q4 = atomicAdd(&g_curV[vb.x], 1);
    int q5 = atomicAdd(&g_curV[vb.y], 1);
    int q6 = atomicAdd(&g_curV[vb.z], 1);
    int q7 = atomicAdd(&g_curV[vb.w], 1);
    g_elistV[q0] = ea.x; g_elistV[q1] = ea.y;
    g_elistV[q2] = ea.z; g_elistV[q3] = ea.w;
    g_elistV[q4] = eb.x; g_elistV[q5] = eb.y;
    g_elistV[q6] = eb.z; g_elistV[q7] = eb.w;
}

// ---------------------------------------------------------------------------
// Pass 1: Xe[e] = mean over incident vertices of Xh[v] (fp16 rows, 256B).
// ---------------------------------------------------------------------------
__global__ __launch_bounds__(256) void pass1_kernel() {
    int e = blockIdx.x * (blockDim.x >> 5) + (threadIdx.x >> 5);
    if (e >= ME) return;
    int lane = threadIdx.x & 31;
    int beg = g_offE[e];
    int cnt = g_histE[e];
    const uint2* X2 = reinterpret_cast<const uint2*>(g_Xh);

    float4 acc = make_float4(0.f, 0.f, 0.f, 0.f);
    for (int base = 0; base < cnt; base += 32) {
        int m = cnt - base; if (m > 32) m = 32;
        int idx = 0;
        if (base + lane < cnt) idx = __ldg(&g_vlistE[beg + base + lane]);
        if (m == 32) {
#pragma unroll 8
            for (int j = 0; j < 32; j++) {
                int v = __shfl_sync(0xffffffffu, idx, j);
                uint2 d = __ldg(&X2[(size_t)v * 32 + lane]);
                float2 f0 = __half22float2(*reinterpret_cast<__half2*>(&d.x));
                float2 f1 = __half22float2(*reinterpret_cast<__half2*>(&d.y));
                acc.x += f0.x; acc.y += f0.y; acc.z += f1.x; acc.w += f1.y;
            }
        } else {
            for (int j = 0; j < m; j++) {
                int v = __shfl_sync(0xffffffffu, idx, j);
                uint2 d = __ldg(&X2[(size_t)v * 32 + lane]);
                float2 f0 = __half22float2(*reinterpret_cast<__half2*>(&d.x));
                float2 f1 = __half22float2(*reinterpret_cast<__half2*>(&d.y));
                acc.x += f0.x; acc.y += f0.y; acc.z += f1.x; acc.w += f1.y;
            }
        }
    }
    float s = (cnt > 0) ? 1.0f / (float)cnt : 0.0f;
    __half2 h0 = __floats2half2_rn(acc.x * s, acc.y * s);
    __half2 h1 = __floats2half2_rn(acc.z * s, acc.w * s);
    uint2 o;
    o.x = *reinterpret_cast<unsigned*>(&h0);
    o.y = *reinterpret_cast<unsigned*>(&h1);
    reinterpret_cast<uint2*>(g_Xe)[(size_t)e * 32 + lane] = o;
}

// ---------------------------------------------------------------------------
// Pass 2 (fused mix): Xi[n] = (1-alpha) * mean_e Xe[e] + alpha * X0[n].
// ---------------------------------------------------------------------------
__global__ __launch_bounds__(256) void pass2_kernel(const float* __restrict__ X0,
                                                    const float* __restrict__ pAlpha) {
    int n = blockIdx.x * (blockDim.x >> 5) + (threadIdx.x >> 5);
    if (n >= NV) return;
    int lane = threadIdx.x & 31;
    int beg = g_offV[n];
    int cnt = g_histV[n];
    const uint2* E2 = reinterpret_cast<const uint2*>(g_Xe);

    float4 acc = make_float4(0.f, 0.f, 0.f, 0.f);
    for (int base = 0; base < cnt; base += 32) {
        int m = cnt - base; if (m > 32) m = 32;
        int idx = 0;
        if (base + lane < cnt) idx = __ldg(&g_elistV[beg + base + lane]);
        if (m == 32) {
#pragma unroll 8
            for (int j = 0; j < 32; j++) {
                int e = __shfl_sync(0xffffffffu, idx, j);
                uint2 d = __ldg(&E2[(size_t)e * 32 + lane]);
                float2 f0 = __half22float2(*reinterpret_cast<__half2*>(&d.x));
                float2 f1 = __half22float2(*reinterpret_cast<__half2*>(&d.y));
                acc.x += f0.x; acc.y += f0.y; acc.z += f1.x; acc.w += f1.y;
            }
        } else {
            for (int j = 0; j < m; j++) {
                int e = __shfl_sync(0xffffffffu, idx, j);
                uint2 d = __ldg(&E2[(size_t)e * 32 + lane]);
                float2 f0 = __half22float2(*reinterpret_cast<__half2*>(&d.x));
                float2 f1 = __half22float2(*reinterpret_cast<__half2*>(&d.y));
                acc.x += f0.x; acc.y += f0.y; acc.z += f1.x; acc.w += f1.y;
            }
        }
    }
    float alpha = __ldg(pAlpha);
    float s = (cnt > 0) ? (1.0f - alpha) / (float)cnt : 0.0f;
    float4 x0 = __ldg(&reinterpret_cast<const float4*>(X0)[(size_t)n * 32 + lane]);
    float4 xi;
    xi.x = acc.x * s + alpha * x0.x;
    xi.y = acc.y * s + alpha * x0.y;
    xi.z = acc.z * s + alpha * x0.z;
    xi.w = acc.w * s + alpha * x0.w;
    reinterpret_cast<float4*>(g_Xi)[(size_t)n * 32 + lane] = xi;
}

// ---------------------------------------------------------------------------
// Final: out = Xi @ Weff^T,  Weff = (1-beta)*I + beta*W.
// ---------------------------------------------------------------------------
#define GR 64

__global__ __launch_bounds__(256) void final_kernel(
    const float* __restrict__ W,
    const float* __restrict__ pBeta,
    float* __restrict__ out) {
    extern __shared__ float Ws[];

    const float beta = __ldg(pBeta);
    const float omb  = 1.0f - beta;
    const int tid  = threadIdx.x;
    const int row0 = blockIdx.x * GR;

    for (int idx = tid; idx < D * D; idx += blockDim.x) {
        int c = idx >> 7;
        int k = idx & 127;
        float w = beta * __ldg(W + idx) + ((c == k) ? omb : 0.0f);
        int c4 = c >> 2, cr = c & 3;
        Ws[k * D + (((c4 ^ (k & 31)) << 2) | cr)] = w;
    }
    __syncthreads();

    const int rowt = tid >> 4;
    const int colt = tid & 15;
    const int g0 = colt * 2;

    int r[4];
#pragma unroll
    for (int i = 0; i < 4; i++) {
        int n = row0 + rowt * 4 + i;
        r[i] = (n < NV) ? n : (NV - 1);
    }

    const float4* A = reinterpret_cast<const float4*>(g_Xi);

    float acc[4][8];
#pragma unroll
    for (int i = 0; i < 4; i++)
#pragma unroll
        for (int j = 0; j < 8; j++) acc[i][j] = 0.0f;

#pragma unroll 4
    for (int k4 = 0; k4 < 32; k4++) {
        float4 a[4];
#pragma unroll
        for (int i = 0; i < 4; i++)
            a[i] = __ldg(&A[(size_t)r[i] * 32 + k4]);

#pragma unroll
        for (int kk = 0; kk < 4; kk++) {
            int k = k4 * 4 + kk;
            int s = k & 31;
            float4 b0 = *reinterpret_cast<const float4*>(&Ws[k * D + ((g0 ^ s) << 2)]);
            float4 b1 = *reinterpret_cast<const float4*>(&Ws[k * D + (((g0 + 1) ^ s) << 2)]);
            float bv[8] = {b0.x, b0.y, b0.z, b0.w, b1.x, b1.y, b1.z, b1.w};
            float av[4];
            av[0] = (kk == 0) ? a[0].x : (kk == 1) ? a[0].y : (kk == 2) ? a[0].z : a[0].w;
            av[1] = (kk == 0) ? a[1].x : (kk == 1) ? a[1].y : (kk == 2) ? a[1].z : a[1].w;
            av[2] = (kk == 0) ? a[2].x : (kk == 1) ? a[2].y : (kk == 2) ? a[2].z : a[2].w;
            av[3] = (kk == 0) ? a[3].x : (kk == 1) ? a[3].y : (kk == 2) ? a[3].z : a[3].w;
#pragma unroll
            for (int i = 0; i < 4; i++)
#pragma unroll
                for (int j = 0; j < 8; j++) acc[i][j] += av[i] * bv[j];
        }
    }

    const int cbase = colt * 8;
#pragma unroll
    for (int i = 0; i < 4; i++) {
        int n = row0 + rowt * 4 + i;
        if (n < NV) {
            float4 o0 = make_float4(acc[i][0], acc[i][1], acc[i][2], acc[i][3]);
            float4 o1 = make_float4(acc[i][4], acc[i][5], acc[i][6], acc[i][7]);
            float4* op = reinterpret_cast<float4*>(out + (size_t)n * D + cbase);
            op[0] = o0;
            op[1] = o1;
        }
    }
}

// ---------------------------------------------------------------------------
extern "C" void kernel_launch(void* const* d_in, const int* in_sizes, int n_in,
                              void* d_out, int out_size) {
    const float* X      = (const float*)d_in[0];
    const float* X0     = (const float*)d_in[1];
    const float* W      = (const float*)d_in[2];
    const float* pAlpha = (const float*)d_in[3];
    const float* pBeta  = (const float*)d_in[4];
    const int*   vertex = (const int*)d_in[5];
    const int*   edges  = (const int*)d_in[6];
    float* out = (float*)d_out;

    convert_kernel<<<(NV * D / 4 + 255) / 256, 256>>>(X);
    zero_hist_kernel<<<(NV + 255) / 256, 256>>>();
    hist_kernel<<<(NNZt / 8 + 255) / 256, 256>>>(vertex, edges);
    scanA_kernel<<<NBLK_E + NBLK_V, 256>>>();
    scanB_kernel<<<1, 128>>>();
    scanC_kernel<<<NBLK_E + NBLK_V, 256>>>();
    permute_kernel<<<(NNZt / 8 + 255) / 256, 256>>>(vertex, edges);

    pass1_kernel<<<(ME * 32 + 255) / 256, 256>>>();
    pass2_kernel<<<(NV * 32 + 255) / 256, 256>>>(X0, pAlpha);

    int smem_bytes = D * D * (int)sizeof(float);  // 65536
    static bool attr_set = false;
    if (!attr_set) {
        cudaFuncSetAttribute(final_kernel,
                             cudaFuncAttributeMaxDynamicSharedMemorySize, smem_bytes);
        attr_set = true;
    }
    final_kernel<<<(NV + GR - 1) / GR, 256, smem_bytes>>>(W, pBeta, out);
}

// round 6
// speedup vs baseline: 1.5002x; 1.5002x over previous
#include <cuda_runtime.h>
#include <cuda_fp16.h>
#include <cstdint>

#define NV   50000
#define ME   10000
#define NNZt 1600000
#define D    128

#define NBLK_E ((ME + 1023) / 1024)   // 10
#define NBLK_V ((NV + 1023) / 1024)   // 49

// ---------------------------------------------------------------------------
// Static device scratch
// ---------------------------------------------------------------------------
__device__ __half g_Xh[NV * D];       // 12.8 MB  fp16 copy of X
__device__ __half g_Xe[ME * D];       // 2.56 MB  edge means (fp16)
__device__ float  g_Xi[NV * D];       // 25.6 MB  mixed vertex features
__device__ int    g_histE[ME];
__device__ int    g_histV[NV];
__device__ int    g_offE[ME];
__device__ int    g_offV[NV];
__device__ int    g_curE[ME];
__device__ int    g_curV[NV];
__device__ int    g_vlistE[NNZt];
__device__ int    g_elistV[NNZt];
__device__ int    g_bsumE[64];
__device__ int    g_bsumV[64];

// ---------------------------------------------------------------------------
// Convert X to fp16
// ---------------------------------------------------------------------------
__global__ void convert_kernel(const float* __restrict__ X) {
    int i = blockIdx.x * blockDim.x + threadIdx.x;
    const int n4 = NV * D / 4;
    if (i >= n4) return;
    float4 v = __ldg(&reinterpret_cast<const float4*>(X)[i]);
    __half2 h0 = __floats2half2_rn(v.x, v.y);
    __half2 h1 = __floats2half2_rn(v.z, v.w);
    uint2 o;
    o.x = *reinterpret_cast<unsigned*>(&h0);
    o.y = *reinterpret_cast<unsigned*>(&h1);
    reinterpret_cast<uint2*>(g_Xh)[i] = o;
}

__global__ void zero_hist_kernel() {
    int i = blockIdx.x * blockDim.x + threadIdx.x;
    if (i < ME) g_histE[i] = 0;
    if (i < NV) g_histV[i] = 0;
}

// ---------------------------------------------------------------------------
// Histogram: 4 entries per thread (R4-proven configuration)
// ---------------------------------------------------------------------------
__global__ void hist_kernel(const int* __restrict__ vertex,
                            const int* __restrict__ edges) {
    int i0 = (blockIdx.x * blockDim.x + threadIdx.x) * 4;
    if (i0 >= NNZt) return;
    int4 v4 = __ldg(reinterpret_cast<const int4*>(vertex + i0));
    int4 e4 = __ldg(reinterpret_cast<const int4*>(edges + i0));
    atomicAdd(&g_histE[e4.x], 1); atomicAdd(&g_histE[e4.y], 1);
    atomicAdd(&g_histE[e4.z], 1); atomicAdd(&g_histE[e4.w], 1);
    atomicAdd(&g_histV[v4.x], 1); atomicAdd(&g_histV[v4.y], 1);
    atomicAdd(&g_histV[v4.z], 1); atomicAdd(&g_histV[v4.w], 1);
}

// ---------------------------------------------------------------------------
// Multi-block exclusive scan, 3 phases (R5-proven, ~8us total)
// ---------------------------------------------------------------------------
__global__ __launch_bounds__(256) void scanA_kernel() {
    int b = blockIdx.x;
    const int* hist; int n, bl; int* bsum;
    if (b < NBLK_E) { hist = g_histE; n = ME; bl = b;          bsum = g_bsumE; }
    else            { hist = g_histV; n = NV; bl = b - NBLK_E; bsum = g_bsumV; }
    int t = threadIdx.x;
    int i0 = bl * 1024 + t * 4;
    int s = 0;
    if (i0 < n) {
        int4 v = *reinterpret_cast<const int4*>(hist + i0);
        s = v.x + v.y + v.z + v.w;
    }
    __shared__ int sm[256];
    sm[t] = s; __syncthreads();
    for (int d = 128; d > 0; d >>= 1) {
        if (t < d) sm[t] += sm[t + d];
        __syncthreads();
    }
    if (t == 0) bsum[bl] = sm[0];
}

__global__ __launch_bounds__(128) void scanB_kernel() {
    __shared__ int sv[64], se[64];
    int t = threadIdx.x;
    int o = 0;
    if (t < 64) { o = (t < NBLK_V) ? g_bsumV[t] : 0; sv[t] = o; }
    else        { int u = t - 64; o = (u < NBLK_E) ? g_bsumE[u] : 0; se[u] = o; }
    __syncthreads();
    for (int d = 1; d < 64; d <<= 1) {
        int x;
        if (t < 64) x = (t >= d) ? sv[t - d] : 0;
        else        { int u = t - 64; x = (u >= d) ? se[u - d] : 0; }
        __syncthreads();
        if (t < 64) sv[t] += x; else se[t - 64] += x;
        __syncthreads();
    }
    if (t < 64) { if (t < NBLK_V) g_bsumV[t] = sv[t] - o; }
    else        { int u = t - 64; if (u < NBLK_E) g_bsumE[u] = se[u] - o; }
}

__global__ __launch_bounds__(256) void scanC_kernel() {
    int b = blockIdx.x;
    const int* hist; int n, bl; int *off, *cur; const int* bsum;
    if (b < NBLK_E) { hist = g_histE; n = ME; bl = b;          off = g_offE; cur = g_curE; bsum = g_bsumE; }
    else            { hist = g_histV; n = NV; bl = b - NBLK_E; off = g_offV; cur = g_curV; bsum = g_bsumV; }
    int t = threadIdx.x;
    int i0 = bl * 1024 + t * 4;
    int4 v = make_int4(0, 0, 0, 0);
    int s = 0;
    if (i0 < n) {
        v = *reinterpret_cast<const int4*>(hist + i0);
        s = v.x + v.y + v.z + v.w;
    }
    __shared__ int sm[256];
    sm[t] = s; __syncthreads();
    for (int d = 1; d < 256; d <<= 1) {
        int x = (t >= d) ? sm[t - d] : 0;
        __syncthreads();
        sm[t] += x;
        __syncthreads();
    }
    if (i0 < n) {
        int run = bsum[bl] + sm[t] - s;  // exclusive prefix
        int4 o;
        o.x = run; run += v.x;
        o.y = run; run += v.y;
        o.z = run; run += v.z;
        o.w = run;
        *reinterpret_cast<int4*>(off + i0) = o;
        *reinterpret_cast<int4*>(cur + i0) = o;
    }
}

// ---------------------------------------------------------------------------
// Permute: 4 entries per thread (R4-proven configuration)
// ---------------------------------------------------------------------------
__global__ void permute_kernel(const int* __restrict__ vertex,
                               const int* __restrict__ edges) {
    int i0 = (blockIdx.x * blockDim.x + threadIdx.x) * 4;
    if (i0 >= NNZt) return;
    int4 v4 = __ldg(reinterpret_cast<const int4*>(vertex + i0));
    int4 e4 = __ldg(reinterpret_cast<const int4*>(edges + i0));
    int p0 = atomicAdd(&g_curE[e4.x], 1);
    int p1 = atomicAdd(&g_curE[e4.y], 1);
    int p2 = atomicAdd(&g_curE[e4.z], 1);
    int p3 = atomicAdd(&g_curE[e4.w], 1);
    g_vlistE[p0] = v4.x; g_vlistE[p1] = v4.y;
    g_vlistE[p2] = v4.z; g_vlistE[p3] = v4.w;
    int q0 = atomicAdd(&g_curV[v4.x], 1);
    int q1 = atomicAdd(&g_curV[v4.y], 1);
    int q2 = atomicAdd(&g_curV[v4.z], 1);
    int q3 = atomicAdd(&g_curV[v4.w], 1);
    g_elistV[q0] = e4.x; g_elistV[q1] = e4.y;
    g_elistV[q2] = e4.z; g_elistV[q3] = e4.w;
}

// ---------------------------------------------------------------------------
// Pass 1: Xe[e] = mean over incident vertices of Xh[v] (fp16 rows, 256B).
// ---------------------------------------------------------------------------
__global__ __launch_bounds__(256) void pass1_kernel() {
    int e = blockIdx.x * (blockDim.x >> 5) + (threadIdx.x >> 5);
    if (e >= ME) return;
    int lane = threadIdx.x & 31;
    int beg = g_offE[e];
    int cnt = g_histE[e];
    const uint2* X2 = reinterpret_cast<const uint2*>(g_Xh);

    float4 acc = make_float4(0.f, 0.f, 0.f, 0.f);
    for (int base = 0; base < cnt; base += 32) {
        int m = cnt - base; if (m > 32) m = 32;
        int idx = 0;
        if (base + lane < cnt) idx = __ldg(&g_vlistE[beg + base + lane]);
        if (m == 32) {
#pragma unroll 8
            for (int j = 0; j < 32; j++) {
                int v = __shfl_sync(0xffffffffu, idx, j);
                uint2 d = __ldg(&X2[(size_t)v * 32 + lane]);
                float2 f0 = __half22float2(*reinterpret_cast<__half2*>(&d.x));
                float2 f1 = __half22float2(*reinterpret_cast<__half2*>(&d.y));
                acc.x += f0.x; acc.y += f0.y; acc.z += f1.x; acc.w += f1.y;
            }
        } else {
            for (int j = 0; j < m; j++) {
                int v = __shfl_sync(0xffffffffu, idx, j);
                uint2 d = __ldg(&X2[(size_t)v * 32 + lane]);
                float2 f0 = __half22float2(*reinterpret_cast<__half2*>(&d.x));
                float2 f1 = __half22float2(*reinterpret_cast<__half2*>(&d.y));
                acc.x += f0.x; acc.y += f0.y; acc.z += f1.x; acc.w += f1.y;
            }
        }
    }
    float s = (cnt > 0) ? 1.0f / (float)cnt : 0.0f;
    __half2 h0 = __floats2half2_rn(acc.x * s, acc.y * s);
    __half2 h1 = __floats2half2_rn(acc.z * s, acc.w * s);
    uint2 o;
    o.x = *reinterpret_cast<unsigned*>(&h0);
    o.y = *reinterpret_cast<unsigned*>(&h1);
    reinterpret_cast<uint2*>(g_Xe)[(size_t)e * 32 + lane] = o;
}

// ---------------------------------------------------------------------------
// Pass 2 (fused mix): Xi[n] = (1-alpha) * mean_e Xe[e] + alpha * X0[n].
// ---------------------------------------------------------------------------
__global__ __launch_bounds__(256) void pass2_kernel(const float* __restrict__ X0,
                                                    const float* __restrict__ pAlpha) {
    int n = blockIdx.x * (blockDim.x >> 5) + (threadIdx.x >> 5);
    if (n >= NV) return;
    int lane = threadIdx.x & 31;
    int beg = g_offV[n];
    int cnt = g_histV[n];
    const uint2* E2 = reinterpret_cast<const uint2*>(g_Xe);

    float4 acc = make_float4(0.f, 0.f, 0.f, 0.f);
    for (int base = 0; base < cnt; base += 32) {
        int m = cnt - base; if (m > 32) m = 32;
        int idx = 0;
        if (base + lane < cnt) idx = __ldg(&g_elistV[beg + base + lane]);
        if (m == 32) {
#pragma unroll 8
            for (int j = 0; j < 32; j++) {
                int e = __shfl_sync(0xffffffffu, idx, j);
                uint2 d = __ldg(&E2[(size_t)e * 32 + lane]);
                float2 f0 = __half22float2(*reinterpret_cast<__half2*>(&d.x));
                float2 f1 = __half22float2(*reinterpret_cast<__half2*>(&d.y));
                acc.x += f0.x; acc.y += f0.y; acc.z += f1.x; acc.w += f1.y;
            }
        } else {
            for (int j = 0; j < m; j++) {
                int e = __shfl_sync(0xffffffffu, idx, j);
                uint2 d = __ldg(&E2[(size_t)e * 32 + lane]);
                float2 f0 = __half22float2(*reinterpret_cast<__half2*>(&d.x));
                float2 f1 = __half22float2(*reinterpret_cast<__half2*>(&d.y));
                acc.x += f0.x; acc.y += f0.y; acc.z += f1.x; acc.w += f1.y;
            }
        }
    }
    float alpha = __ldg(pAlpha);
    float s = (cnt > 0) ? (1.0f - alpha) / (float)cnt : 0.0f;
    float4 x0 = __ldg(&reinterpret_cast<const float4*>(X0)[(size_t)n * 32 + lane]);
    float4 xi;
    xi.x = acc.x * s + alpha * x0.x;
    xi.y = acc.y * s + alpha * x0.y;
    xi.z = acc.z * s + alpha * x0.z;
    xi.w = acc.w * s + alpha * x0.w;
    reinterpret_cast<float4*>(g_Xi)[(size_t)n * 32 + lane] = xi;
}

// ---------------------------------------------------------------------------
// Final: out = Xi @ Weff^T,  Weff = (1-beta)*I + beta*W.
// ---------------------------------------------------------------------------
#define GR 64

__global__ __launch_bounds__(256) void final_kernel(
    const float* __restrict__ W,
    const float* __restrict__ pBeta,
    float* __restrict__ out) {
    extern __shared__ float Ws[];

    const float beta = __ldg(pBeta);
    const float omb  = 1.0f - beta;
    const int tid  = threadIdx.x;
    const int row0 = blockIdx.x * GR;

    for (int idx = tid; idx < D * D; idx += blockDim.x) {
        int c = idx >> 7;
        int k = idx & 127;
        float w = beta * __ldg(W + idx) + ((c == k) ? omb : 0.0f);
        int c4 = c >> 2, cr = c & 3;
        Ws[k * D + (((c4 ^ (k & 31)) << 2) | cr)] = w;
    }
    __syncthreads();

    const int rowt = tid >> 4;
    const int colt = tid & 15;
    const int g0 = colt * 2;

    int r[4];
#pragma unroll
    for (int i = 0; i < 4; i++) {
        int n = row0 + rowt * 4 + i;
        r[i] = (n < NV) ? n : (NV - 1);
    }

    const float4* A = reinterpret_cast<const float4*>(g_Xi);

    float acc[4][8];
#pragma unroll
    for (int i = 0; i < 4; i++)
#pragma unroll
        for (int j = 0; j < 8; j++) acc[i][j] = 0.0f;

#pragma unroll 4
    for (int k4 = 0; k4 < 32; k4++) {
        float4 a[4];
#pragma unroll
        for (int i = 0; i < 4; i++)
            a[i] = __ldg(&A[(size_t)r[i] * 32 + k4]);

#pragma unroll
        for (int kk = 0; kk < 4; kk++) {
            int k = k4 * 4 + kk;
            int s = k & 31;
            float4 b0 = *reinterpret_cast<const float4*>(&Ws[k * D + ((g0 ^ s) << 2)]);
            float4 b1 = *reinterpret_cast<const float4*>(&Ws[k * D + (((g0 + 1) ^ s) << 2)]);
            float bv[8] = {b0.x, b0.y, b0.z, b0.w, b1.x, b1.y, b1.z, b1.w};
            float av[4];
            av[0] = (kk == 0) ? a[0].x : (kk == 1) ? a[0].y : (kk == 2) ? a[0].z : a[0].w;
            av[1] = (kk == 0) ? a[1].x : (kk == 1) ? a[1].y : (kk == 2) ? a[1].z : a[1].w;
            av[2] = (kk == 0) ? a[2].x : (kk == 1) ? a[2].y : (kk == 2) ? a[2].z : a[2].w;
            av[3] = (kk == 0) ? a[3].x : (kk == 1) ? a[3].y : (kk == 2) ? a[3].z : a[3].w;
#pragma unroll
            for (int i = 0; i < 4; i++)
#pragma unroll
                for (int j = 0; j < 8; j++) acc[i][j] += av[i] * bv[j];
        }
    }

    const int cbase = colt * 8;
#pragma unroll
    for (int i = 0; i < 4; i++) {
        int n = row0 + rowt * 4 + i;
        if (n < NV) {
            float4 o0 = make_float4(acc[i][0], acc[i][1], acc[i][2], acc[i][3]);
            float4 o1 = make_float4(acc[i][4], acc[i][5], acc[i][6], acc[i][7]);
            float4* op = reinterpret_cast<float4*>(out + (size_t)n * D + cbase);
            op[0] = o0;
            op[1] = o1;
        }
    }
}

// ---------------------------------------------------------------------------
extern "C" void kernel_launch(void* const* d_in, const int* in_sizes, int n_in,
                              void* d_out, int out_size) {
    const float* X      = (const float*)d_in[0];
    const float* X0     = (const float*)d_in[1];
    const float* W      = (const float*)d_in[2];
    const float* pAlpha = (const float*)d_in[3];
    const float* pBeta  = (const float*)d_in[4];
    const int*   vertex = (const int*)d_in[5];
    const int*   edges  = (const int*)d_in[6];
    float* out = (float*)d_out;

    convert_kernel<<<(NV * D / 4 + 255) / 256, 256>>>(X);
    zero_hist_kernel<<<(NV + 255) / 256, 256>>>();
    hist_kernel<<<(NNZt / 4 + 255) / 256, 256>>>(vertex, edges);
    scanA_kernel<<<NBLK_E + NBLK_V, 256>>>();
    scanB_kernel<<<1, 128>>>();
    scanC_kernel<<<NBLK_E + NBLK_V, 256>>>();
    permute_kernel<<<(NNZt / 4 + 255) / 256, 256>>>(vertex, edges);

    pass1_kernel<<<(ME * 32 + 255) / 256, 256>>>();
    pass2_kernel<<<(NV * 32 + 255) / 256, 256>>>(X0, pAlpha);

    int smem_bytes = D * D * (int)sizeof(float);  // 65536
    static bool attr_set = false;
    if (!attr_set) {
        cudaFuncSetAttribute(final_kernel,
                             cudaFuncAttributeMaxDynamicSharedMemorySize, smem_bytes);
        attr_set = true;
    }
    final_kernel<<<(NV + GR - 1) / GR, 256, smem_bytes>>>(W, pBeta, out);
}

// round 7
// speedup vs baseline: 1.6758x; 1.1171x over previous
#include <cuda_runtime.h>
#include <cuda_fp16.h>
#include <mma.h>
#include <cstdint>

using namespace nvcuda;

#define NV   50000
#define ME   10000
#define NNZt 1600000
#define D    128

#define NBLK_E ((ME + 1023) / 1024)   // 10
#define NBLK_V ((NV + 1023) / 1024)   // 49

// ---------------------------------------------------------------------------
// Static device scratch
// ---------------------------------------------------------------------------
__device__ __half g_Xh[NV * D];       // 12.8 MB  fp16 copy of X
__device__ __half g_Xe[ME * D];       // 2.56 MB  edge means (fp16)
__device__ __half g_Xih[NV * D];      // 12.8 MB  mixed vertex features (fp16)
__device__ int    g_histE[ME];
__device__ int    g_histV[NV];
__device__ int    g_offE[ME];
__device__ int    g_offV[NV];
__device__ int    g_curE[ME];
__device__ int    g_curV[NV];
__device__ int    g_vlistE[NNZt];
__device__ int    g_elistV[NNZt];
__device__ int    g_bsumE[64];
__device__ int    g_bsumV[64];

// ---------------------------------------------------------------------------
// Prep: convert X to fp16 AND zero histograms (fused)
// ---------------------------------------------------------------------------
__global__ void prep_kernel(const float* __restrict__ X) {
    int i = blockIdx.x * blockDim.x + threadIdx.x;
    const int n4 = NV * D / 4;
    if (i < n4) {
        float4 v = __ldg(&reinterpret_cast<const float4*>(X)[i]);
        __half2 h0 = __floats2half2_rn(v.x, v.y);
        __half2 h1 = __floats2half2_rn(v.z, v.w);
        uint2 o;
        o.x = *reinterpret_cast<unsigned*>(&h0);
        o.y = *reinterpret_cast<unsigned*>(&h1);
        reinterpret_cast<uint2*>(g_Xh)[i] = o;
    }
    if (i < ME) g_histE[i] = 0;
    if (i < NV) g_histV[i] = 0;
}

// ---------------------------------------------------------------------------
// Histogram: 4 entries per thread (R4-proven configuration)
// ---------------------------------------------------------------------------
__global__ void hist_kernel(const int* __restrict__ vertex,
                            const int* __restrict__ edges) {
    int i0 = (blockIdx.x * blockDim.x + threadIdx.x) * 4;
    if (i0 >= NNZt) return;
    int4 v4 = __ldg(reinterpret_cast<const int4*>(vertex + i0));
    int4 e4 = __ldg(reinterpret_cast<const int4*>(edges + i0));
    atomicAdd(&g_histE[e4.x], 1); atomicAdd(&g_histE[e4.y], 1);
    atomicAdd(&g_histE[e4.z], 1); atomicAdd(&g_histE[e4.w], 1);
    atomicAdd(&g_histV[v4.x], 1); atomicAdd(&g_histV[v4.y], 1);
    atomicAdd(&g_histV[v4.z], 1); atomicAdd(&g_histV[v4.w], 1);
}

// ---------------------------------------------------------------------------
// Multi-block exclusive scan, 3 phases (R5/R6-proven, ~8us total)
// ---------------------------------------------------------------------------
__global__ __launch_bounds__(256) void scanA_kernel() {
    int b = blockIdx.x;
    const int* hist; int n, bl; int* bsum;
    if (b < NBLK_E) { hist = g_histE; n = ME; bl = b;          bsum = g_bsumE; }
    else            { hist = g_histV; n = NV; bl = b - NBLK_E; bsum = g_bsumV; }
    int t = threadIdx.x;
    int i0 = bl * 1024 + t * 4;
    int s = 0;
    if (i0 < n) {
        int4 v = *reinterpret_cast<const int4*>(hist + i0);
        s = v.x + v.y + v.z + v.w;
    }
    __shared__ int sm[256];
    sm[t] = s; __syncthreads();
    for (int d = 128; d > 0; d >>= 1) {
        if (t < d) sm[t] += sm[t + d];
        __syncthreads();
    }
    if (t == 0) bsum[bl] = sm[0];
}

__global__ __launch_bounds__(128) void scanB_kernel() {
    __shared__ int sv[64], se[64];
    int t = threadIdx.x;
    int o = 0;
    if (t < 64) { o = (t < NBLK_V) ? g_bsumV[t] : 0; sv[t] = o; }
    else        { int u = t - 64; o = (u < NBLK_E) ? g_bsumE[u] : 0; se[u] = o; }
    __syncthreads();
    for (int d = 1; d < 64; d <<= 1) {
        int x;
        if (t < 64) x = (t >= d) ? sv[t - d] : 0;
        else        { int u = t - 64; x = (u >= d) ? se[u - d] : 0; }
        __syncthreads();
        if (t < 64) sv[t] += x; else se[t - 64] += x;
        __syncthreads();
    }
    if (t < 64) { if (t < NBLK_V) g_bsumV[t] = sv[t] - o; }
    else        { int u = t - 64; if (u < NBLK_E) g_bsumE[u] = se[u] - o; }
}

__global__ __launch_bounds__(256) void scanC_kernel() {
    int b = blockIdx.x;
    const int* hist; int n, bl; int *off, *cur; const int* bsum;
    if (b < NBLK_E) { hist = g_histE; n = ME; bl = b;          off = g_offE; cur = g_curE; bsum = g_bsumE; }
    else            { hist = g_histV; n = NV; bl = b - NBLK_E; off = g_offV; cur = g_curV; bsum = g_bsumV; }
    int t = threadIdx.x;
    int i0 = bl * 1024 + t * 4;
    int4 v = make_int4(0, 0, 0, 0);
    int s = 0;
    if (i0 < n) {
        v = *reinterpret_cast<const int4*>(hist + i0);
        s = v.x + v.y + v.z + v.w;
    }
    __shared__ int sm[256];
    sm[t] = s; __syncthreads();
    for (int d = 1; d < 256; d <<= 1) {
        int x = (t >= d) ? sm[t - d] : 0;
        __syncthreads();
        sm[t] += x;
        __syncthreads();
    }
    if (i0 < n) {
        int run = bsum[bl] + sm[t] - s;  // exclusive prefix
        int4 o;
        o.x = run; run += v.x;
        o.y = run; run += v.y;
        o.z = run; run += v.z;
        o.w = run;
        *reinterpret_cast<int4*>(off + i0) = o;
        *reinterpret_cast<int4*>(cur + i0) = o;
    }
}

// ---------------------------------------------------------------------------
// Permute: 4 entries per thread (R4-proven configuration)
// ---------------------------------------------------------------------------
__global__ void permute_kernel(const int* __restrict__ vertex,
                               const int* __restrict__ edges) {
    int i0 = (blockIdx.x * blockDim.x + threadIdx.x) * 4;
    if (i0 >= NNZt) return;
    int4 v4 = __ldg(reinterpret_cast<const int4*>(vertex + i0));
    int4 e4 = __ldg(reinterpret_cast<const int4*>(edges + i0));
    int p0 = atomicAdd(&g_curE[e4.x], 1);
    int p1 = atomicAdd(&g_curE[e4.y], 1);
    int p2 = atomicAdd(&g_curE[e4.z], 1);
    int p3 = atomicAdd(&g_curE[e4.w], 1);
    g_vlistE[p0] = v4.x; g_vlistE[p1] = v4.y;
    g_vlistE[p2] = v4.z; g_vlistE[p3] = v4.w;
    int q0 = atomicAdd(&g_curV[v4.x], 1);
    int q1 = atomicAdd(&g_curV[v4.y], 1);
    int q2 = atomicAdd(&g_curV[v4.z], 1);
    int q3 = atomicAdd(&g_curV[v4.w], 1);
    g_elistV[q0] = e4.x; g_elistV[q1] = e4.y;
    g_elistV[q2] = e4.z; g_elistV[q3] = e4.w;
}

// ---------------------------------------------------------------------------
// Pass 1: Xe[e] = mean over incident vertices of Xh[v] (fp16 rows, 256B).
// ---------------------------------------------------------------------------
__global__ __launch_bounds__(256) void pass1_kernel() {
    int e = blockIdx.x * (blockDim.x >> 5) + (threadIdx.x >> 5);
    if (e >= ME) return;
    int lane = threadIdx.x & 31;
    int beg = g_offE[e];
    int cnt = g_histE[e];
    const uint2* X2 = reinterpret_cast<const uint2*>(g_Xh);

    float4 acc = make_float4(0.f, 0.f, 0.f, 0.f);
    for (int base = 0; base < cnt; base += 32) {
        int m = cnt - base; if (m > 32) m = 32;
        int idx = 0;
        if (base + lane < cnt) idx = __ldg(&g_vlistE[beg + base + lane]);
        if (m == 32) {
#pragma unroll 8
            for (int j = 0; j < 32; j++) {
                int v = __shfl_sync(0xffffffffu, idx, j);
                uint2 d = __ldg(&X2[(size_t)v * 32 + lane]);
                float2 f0 = __half22float2(*reinterpret_cast<__half2*>(&d.x));
                float2 f1 = __half22float2(*reinterpret_cast<__half2*>(&d.y));
                acc.x += f0.x; acc.y += f0.y; acc.z += f1.x; acc.w += f1.y;
            }
        } else {
            for (int j = 0; j < m; j++) {
                int v = __shfl_sync(0xffffffffu, idx, j);
                uint2 d = __ldg(&X2[(size_t)v * 32 + lane]);
                float2 f0 = __half22float2(*reinterpret_cast<__half2*>(&d.x));
                float2 f1 = __half22float2(*reinterpret_cast<__half2*>(&d.y));
                acc.x += f0.x; acc.y += f0.y; acc.z += f1.x; acc.w += f1.y;
            }
        }
    }
    float s = (cnt > 0) ? 1.0f / (float)cnt : 0.0f;
    __half2 h0 = __floats2half2_rn(acc.x * s, acc.y * s);
    __half2 h1 = __floats2half2_rn(acc.z * s, acc.w * s);
    uint2 o;
    o.x = *reinterpret_cast<unsigned*>(&h0);
    o.y = *reinterpret_cast<unsigned*>(&h1);
    reinterpret_cast<uint2*>(g_Xe)[(size_t)e * 32 + lane] = o;
}

// ---------------------------------------------------------------------------
// Pass 2 (fused mix): Xi[n] = (1-alpha) * mean_e Xe[e] + alpha * X0[n].
// Output in fp16 for the HMMA epilogue.
// ---------------------------------------------------------------------------
__global__ __launch_bounds__(256) void pass2_kernel(const float* __restrict__ X0,
                                                    const float* __restrict__ pAlpha) {
    int n = blockIdx.x * (blockDim.x >> 5) + (threadIdx.x >> 5);
    if (n >= NV) return;
    int lane = threadIdx.x & 31;
    int beg = g_offV[n];
    int cnt = g_histV[n];
    const uint2* E2 = reinterpret_cast<const uint2*>(g_Xe);

    float4 acc = make_float4(0.f, 0.f, 0.f, 0.f);
    for (int base = 0; base < cnt; base += 32) {
        int m = cnt - base; if (m > 32) m = 32;
        int idx = 0;
        if (base + lane < cnt) idx = __ldg(&g_elistV[beg + base + lane]);
        if (m == 32) {
#pragma unroll 8
            for (int j = 0; j < 32; j++) {
                int e = __shfl_sync(0xffffffffu, idx, j);
                uint2 d = __ldg(&E2[(size_t)e * 32 + lane]);
                float2 f0 = __half22float2(*reinterpret_cast<__half2*>(&d.x));
                float2 f1 = __half22float2(*reinterpret_cast<__half2*>(&d.y));
                acc.x += f0.x; acc.y += f0.y; acc.z += f1.x; acc.w += f1.y;
            }
        } else {
            for (int j = 0; j < m; j++) {
                int e = __shfl_sync(0xffffffffu, idx, j);
                uint2 d = __ldg(&E2[(size_t)e * 32 + lane]);
                float2 f0 = __half22float2(*reinterpret_cast<__half2*>(&d.x));
                float2 f1 = __half22float2(*reinterpret_cast<__half2*>(&d.y));
                acc.x += f0.x; acc.y += f0.y; acc.z += f1.x; acc.w += f1.y;
            }
        }
    }
    float alpha = __ldg(pAlpha);
    float s = (cnt > 0) ? (1.0f - alpha) / (float)cnt : 0.0f;
    float4 x0 = __ldg(&reinterpret_cast<const float4*>(X0)[(size_t)n * 32 + lane]);
    __half2 h0 = __floats2half2_rn(acc.x * s + alpha * x0.x,
                                   acc.y * s + alpha * x0.y);
    __half2 h1 = __floats2half2_rn(acc.z * s + alpha * x0.z,
                                   acc.w * s + alpha * x0.w);
    uint2 o;
    o.x = *reinterpret_cast<unsigned*>(&h0);
    o.y = *reinterpret_cast<unsigned*>(&h1);
    reinterpret_cast<uint2*>(g_Xih)[(size_t)n * 32 + lane] = o;
}

// ---------------------------------------------------------------------------
// Final (HMMA): out = Xi @ Weff^T,  Weff = (1-beta)*I + beta*W.
// 64 rows x 128 cols per block, 8 warps; warp = 16 rows x 64 cols = 4 wmma
// accumulators. A (fp16) loaded from global (row-major, ld=128); B = Weff
// in smem [c][k] row-major == col-major (k,c) with ld=128. fp32 accum.
// 50000 = 781*64 + 16: last block has exactly one active 16-row warp pair.
// ---------------------------------------------------------------------------
#define GR 64

__global__ __launch_bounds__(256) void final_kernel(
    const float* __restrict__ W,
    const float* __restrict__ pBeta,
    float* __restrict__ out) {
    __shared__ __half Ws[D * D];  // Weff[c][k] row-major, 32 KB

    const float beta = __ldg(pBeta);
    const float omb  = 1.0f - beta;
    const int tid = threadIdx.x;

    for (int idx = tid; idx < D * D; idx += 256) {
        int c = idx >> 7;
        int k = idx & 127;
        float w = beta * __ldg(W + idx) + ((c == k) ? omb : 0.0f);
        Ws[idx] = __float2half(w);
    }
    __syncthreads();

    const int warp = tid >> 5;
    const int wrow = warp >> 1;           // 0..3: 16-row tile within block
    const int wcol = (warp & 1) * 4;      // 0 or 4: first 16-col tile index
    const int row0 = blockIdx.x * GR + wrow * 16;
    if (row0 + 16 > NV) return;           // idle warps in the last block

    wmma::fragment<wmma::accumulator, 16, 16, 16, float> c_frag[4];
#pragma unroll
    for (int j = 0; j < 4; j++) wmma::fill_fragment(c_frag[j], 0.0f);

    const __half* A = g_Xih;
#pragma unroll
    for (int k = 0; k < 8; k++) {
        wmma::fragment<wmma::matrix_a, 16, 16, 16, __half, wmma::row_major> a_frag;
        wmma::load_matrix_sync(a_frag, A + (size_t)row0 * D + k * 16, D);
#pragma unroll
        for (int j = 0; j < 4; j++) {
            wmma::fragment<wmma::matrix_b, 16, 16, 16, __half, wmma::col_major> b_frag;
            wmma::load_matrix_sync(b_frag, Ws + (wcol + j) * 16 * D + k * 16, D);
            wmma::mma_sync(c_frag[j], a_frag, b_frag, c_frag[j]);
        }
    }

#pragma unroll
    for (int j = 0; j < 4; j++) {
        wmma::store_matrix_sync(out + (size_t)row0 * D + (wcol + j) * 16,
                                c_frag[j], D, wmma::mem_row_major);
    }
}

// ---------------------------------------------------------------------------
extern "C" void kernel_launch(void* const* d_in, const int* in_sizes, int n_in,
                              void* d_out, int out_size) {
    const float* X      = (const float*)d_in[0];
    const float* X0     = (const float*)d_in[1];
    const float* W      = (const float*)d_in[2];
    const float* pAlpha = (const float*)d_in[3];
    const float* pBeta  = (const float*)d_in[4];
    const int*   vertex = (const int*)d_in[5];
    const int*   edges  = (const int*)d_in[6];
    float* out = (float*)d_out;

    prep_kernel<<<(NV * D / 4 + 255) / 256, 256>>>(X);
    hist_kernel<<<(NNZt / 4 + 255) / 256, 256>>>(vertex, edges);
    scanA_kernel<<<NBLK_E + NBLK_V, 256>>>();
    scanB_kernel<<<1, 128>>>();
    scanC_kernel<<<NBLK_E + NBLK_V, 256>>>();
    permute_kernel<<<(NNZt / 4 + 255) / 256, 256>>>(vertex, edges);

    pass1_kernel<<<(ME * 32 + 255) / 256, 256>>>();
    pass2_kernel<<<(NV * 32 + 255) / 256, 256>>>(X0, pAlpha);

    final_kernel<<<(NV + GR - 1) / GR, 256>>>(W, pBeta, out);
}